// round 8
// baseline (speedup 1.0000x reference)
#include <cuda_runtime.h>

// Shapes (fixed by the problem)
#define B_   4
#define N_   128
#define M_   128
#define D_   256
#define BD_  1024
#define R_   (B_ * N_)          // 512 flattened (b,n) rows

#define TAIL_BLOCKS  256        // blocks 0..255: tail role (2 rows each)
#define K1_BLOCKS    8192       // blocks 256..8447: stream role (8 A-rows each)
#define STRIPE_BLKS  2048       // k1 blocks per 64-d stripe
#define STRIPE_CNT   4

// Scratch (no cudaMalloc allowed)
__device__ float g_Aprime[D_ * D_];   // 256 KB: A'[d,e]
__device__ int   g_ctr[STRIPE_CNT];   // per-stripe completion counters (zero-init)
__device__ int   g_tail_done;         // tail-block completion counter (zero-init)

__device__ __forceinline__ int ld_cg_int(const int* p) {
    int v;
    asm volatile("ld.global.cg.b32 %0, [%1];" : "=r"(v) : "l"(p));
    return v;
}

// ---------------------------------------------------------------------------
// Single kernel, block-role specialization.
//  k1 role  : A'[row] = dot(A[row,:], W) for 8 consecutive rows (1/warp),
//             linear 268 MB DRAM stream; signals per-64-d-stripe counters.
//  tail role: resident from wave 1. Stage A consumes A' stripe-by-stripe as
//             the counters land (overlapped with the stream): T[2][256].
//             Stage B: S[2][128] = T @ Y[b]^T + bias. Runs right after the
//             last stripe with zero launch gap.
// ---------------------------------------------------------------------------
__global__ __launch_bounds__(256, 6) void uni(
    const float4* __restrict__ A4,   // [65536 rows][256 float4]
    const float4* __restrict__ W4,   // [256 float4]
    const float4* __restrict__ X4,   // [512][64] float4
    const float4* __restrict__ Y4,   // [512][64] float4
    const float* __restrict__ bias,  // [1]
    float* __restrict__ Ap,          // [65536]
    float* __restrict__ S)           // [512*128]
{
    int tid = threadIdx.x;

    if (blockIdx.x >= TAIL_BLOCKS) {
        // ================= k1 stream role =================
        __shared__ float4 ws[BD_ / 4];           // 4 KB W
        ws[tid] = W4[tid];
        __syncthreads();

        int kbid = blockIdx.x - TAIL_BLOCKS;     // 0..8191
        int lane = tid & 31;
        int row  = kbid * 8 + (tid >> 5);        // 1 row per warp
        const float4* rp = A4 + (size_t)row * (BD_ / 4);

        float s = 0.0f;
#pragma unroll
        for (int i = 0; i < 8; ++i) {
            float4 a = __ldcs(&rp[lane + i * 32]);
            float4 w = ws[lane + i * 32];
            s += a.x * w.x + a.y * w.y;
            s += a.z * w.z + a.w * w.w;
        }
#pragma unroll
        for (int o = 16; o > 0; o >>= 1)
            s += __shfl_xor_sync(0xFFFFFFFFu, s, o);
        if (lane == 0) {
            Ap[row] = s;
            __threadfence();                     // make Ap visible device-wide
        }
        __syncthreads();                          // all 8 rows stored+fenced
        if (tid == 0)
            atomicAdd(&g_ctr[kbid >> 11], 1);    // stripe = kbid/2048
        return;
    }

    // ================= tail role =================
    int r0 = blockIdx.x * 2;                     // 2 rows, same b
    int b  = r0 >> 7;

    __shared__ float xs[2][D_];                  // X rows
    __shared__ float ts[2][D_];                  // T rows
    __shared__ float pp[2][2][128];              // stage-B half partials

    if (tid < 128) {                             // X tile: 2 rows x 64 float4
        int ri = tid >> 6, c = tid & 63;
        float4 v = X4[(size_t)(r0 + ri) * (D_ / 4) + c];
        xs[ri][4 * c + 0] = v.x;
        xs[ri][4 * c + 1] = v.y;
        xs[ri][4 * c + 2] = v.z;
        xs[ri][4 * c + 3] = v.w;
    }
    __syncthreads();

    // ---- Stage A: T[r, e=tid] = sum_d X[r,d]*A'[d,e], stripe by stripe ----
    float a0 = 0.f, a1 = 0.f;
#pragma unroll
    for (int sIdx = 0; sIdx < STRIPE_CNT; ++sIdx) {
        if (tid == 0) {                          // others HW-sleep at barrier
            while (ld_cg_int(&g_ctr[sIdx]) < STRIPE_BLKS)
                __nanosleep(1024);
            __threadfence();
        }
        __syncthreads();                         // stripe sIdx of A' is ready

        int d0 = sIdx * 64;
#pragma unroll 8
        for (int i = 0; i < 64; ++i) {
            int d = d0 + i;
            float av = __ldcg(&Ap[(size_t)d * D_ + tid]);  // coalesced over e
            a0 = fmaf(xs[0][d], av, a0);
            a1 = fmaf(xs[1][d], av, a1);
        }
    }
    ts[0][tid] = a0;
    ts[1][tid] = a1;
    __syncthreads();

    // ---- Stage B: S[r,m] = sum_e T[r,e]*Y[b,m,e] + bias ----
    {
        int m = tid & 127;
        int h = tid >> 7;                        // e-half
        const float4* y = Y4 + (size_t)(b * M_ + m) * (D_ / 4) + h * 32;

        float u0 = 0.f, u1 = 0.f;
#pragma unroll
        for (int i = 0; i < 32; ++i) {
            float4 yv = y[i];
            int e = h * 128 + 4 * i;
            u0 = fmaf(ts[0][e + 0], yv.x, u0);
            u0 = fmaf(ts[0][e + 1], yv.y, u0);
            u0 = fmaf(ts[0][e + 2], yv.z, u0);
            u0 = fmaf(ts[0][e + 3], yv.w, u0);
            u1 = fmaf(ts[1][e + 0], yv.x, u1);
            u1 = fmaf(ts[1][e + 1], yv.y, u1);
            u1 = fmaf(ts[1][e + 2], yv.z, u1);
            u1 = fmaf(ts[1][e + 3], yv.w, u1);
        }
        pp[0][h][m] = u0;
        pp[1][h][m] = u1;
        __syncthreads();

        int rr = tid >> 7;                       // combine halves
        float out = pp[rr][0][m] + pp[rr][1][m] + bias[0];
        S[(size_t)(r0 + rr) * M_ + m] = out;
    }

    // ---- counter self-reset for next graph replay (deterministic) ----
    __syncthreads();
    if (tid == 0) {
        __threadfence();
        int v = atomicAdd(&g_tail_done, 1);
        if (v == TAIL_BLOCKS - 1) {              // last tail block; all k1 done
            g_ctr[0] = 0; g_ctr[1] = 0; g_ctr[2] = 0; g_ctr[3] = 0;
            g_tail_done = 0;
            __threadfence();
        }
    }
}

// ---------------------------------------------------------------------------
extern "C" void kernel_launch(void* const* d_in, const int* in_sizes, int n_in,
                              void* d_out, int out_size)
{
    const float* X  = (const float*)d_in[0];   // [4,128,256]
    const float* Y  = (const float*)d_in[1];   // [4,128,256]
    const float* A  = (const float*)d_in[2];   // [256,256,1024]
    const float* W  = (const float*)d_in[3];   // [1,1024]
    const float* bb = (const float*)d_in[4];   // [1]
    float* S = (float*)d_out;                  // [4,128,128]

    float* Ap;  cudaGetSymbolAddress((void**)&Ap, g_Aprime);

    uni<<<TAIL_BLOCKS + K1_BLOCKS, 256>>>(
        (const float4*)A, (const float4*)W, (const float4*)X,
        (const float4*)Y, bb, Ap, S);
}

// round 9
// speedup vs baseline: 1.3943x; 1.3943x over previous
#include <cuda_runtime.h>

// Shapes (fixed by the problem)
#define B_   4
#define N_   128
#define M_   128
#define D_   256
#define BD_  1024
#define R_   (B_ * N_)        // 512 flattened (b,n) rows

// Scratch (no cudaMalloc allowed)
__device__ float g_Aprime[D_ * D_];   // 256 KB: A'[d,e] = sum_k A[d,e,k]*W[k]

// ---------------------------------------------------------------------------
// Kernel 1: A'[row] = dot(A[row, :], W[:]); row = d*256 + e.
// ONE row per warp, linear 268 MB DRAM stream (measured 81% DRAM / 42.3us —
// at the practical roofline). __ldcs evict-first; W staged in smem.
// UNTOUCHED — every attempt to co-locate work with this stream regressed.
// ---------------------------------------------------------------------------
__global__ __launch_bounds__(256) void k1_fold_w(
    const float4* __restrict__ A4,   // [65536 rows][256 float4]
    const float4* __restrict__ W4,   // [256 float4]
    float* __restrict__ Ap)          // [65536]
{
    __shared__ float4 ws[BD_ / 4];   // 4 KB
    ws[threadIdx.x] = W4[threadIdx.x];
    __syncthreads();

    int warp = (blockIdx.x * blockDim.x + threadIdx.x) >> 5;   // 0..65535
    int lane = threadIdx.x & 31;
    const float4* row = A4 + (size_t)warp * (BD_ / 4);

    float s = 0.0f;
#pragma unroll
    for (int i = 0; i < 8; ++i) {
        float4 a = __ldcs(&row[lane + i * 32]);
        float4 w = ws[lane + i * 32];
        s += a.x * w.x + a.y * w.y;
        s += a.z * w.z + a.w * w.w;
    }
#pragma unroll
    for (int o = 16; o > 0; o >>= 1)
        s += __shfl_xor_sync(0xFFFFFFFFu, s, o);
    if (lane == 0) Ap[warp] = s;
}

// ---------------------------------------------------------------------------
// Fused tail (PDL secondary): per block 4 r-rows (same b), 1024 threads.
// Prologue (X smem load, Y L2 prefetch, bias) runs BEFORE
// cudaGridDependencySynchronize() -> overlapped with k1's drain; the launch
// gap disappears. Stages A/B identical to the proven R6 kernel.
// ---------------------------------------------------------------------------
__global__ __launch_bounds__(1024) void k23_fused(
    const float4* __restrict__ X4,   // [512][64] float4
    const float* __restrict__ Ap,    // [256*256]
    const float4* __restrict__ Y4,   // [512][64] float4
    const float* __restrict__ bias,  // [1]
    float* __restrict__ S)           // [512*128]
{
    int r0 = blockIdx.x * 4;
    int b  = r0 >> 7;
    int tid = threadIdx.x;

    __shared__ float  xs[4][D_];        // 4 KB  X tile
    __shared__ float  ps[4][4][D_];     // 16 KB partials [dq][r][e]
    __shared__ float4 ts4[4][D_ / 4];   // 4 KB  final T rows
    __shared__ float  sbias;

    // ---- k1-independent prologue (overlaps primary under PDL) ----
    if (tid < 256) {                    // X tile: 4 rows x 64 float4
        int ri = tid >> 6, c = tid & 63;
        float4 v = X4[(size_t)(r0 + ri) * (D_ / 4) + c];
        xs[ri][4 * c + 0] = v.x;
        xs[ri][4 * c + 1] = v.y;
        xs[ri][4 * c + 2] = v.z;
        xs[ri][4 * c + 3] = v.w;
    }
    if (tid == 0) sbias = bias[0];
    {   // prefetch this block's Y[b] slab (128 KB = 1024 lines) into L2
        const char* yb = (const char*)(Y4 + (size_t)b * M_ * (D_ / 4));
        asm volatile("prefetch.global.L2 [%0];" :: "l"(yb + (size_t)tid * 128));
    }

    // ---- wait for k1 (programmatic dependency; no-op if launched plainly) --
#if __CUDA_ARCH__ >= 900
    cudaGridDependencySynchronize();
#endif
    __syncthreads();

    // ---- Stage A: T[4][256] = X_tile @ A' ----
    {
        int e  = tid & 255;
        int dq = tid >> 8;               // 0..3
        int d0 = dq * 64;
        float a0 = 0.f, a1 = 0.f, a2 = 0.f, a3 = 0.f;
#pragma unroll 8
        for (int i = 0; i < 64; ++i) {
            int d = d0 + i;
            float av = Ap[(size_t)d * D_ + e];   // coalesced over e, L2-resident
            float x0 = xs[0][d], x1 = xs[1][d], x2 = xs[2][d], x3 = xs[3][d];
            a0 = fmaf(x0, av, a0);
            a1 = fmaf(x1, av, a1);
            a2 = fmaf(x2, av, a2);
            a3 = fmaf(x3, av, a3);
        }
        ps[dq][0][e] = a0;
        ps[dq][1][e] = a1;
        ps[dq][2][e] = a2;
        ps[dq][3][e] = a3;
    }
    __syncthreads();

    // reduce over dq: thread -> (r = tid>>8, e = tid&255)
    {
        int r = tid >> 8;
        int e = tid & 255;
        float s = ps[0][r][e] + ps[1][r][e] + ps[2][r][e] + ps[3][r][e];
        ((float*)ts4)[r * D_ + e] = s;
    }
    __syncthreads();

    // ---- Stage B: S[4][128] = T @ Y[b]^T + bias ----
    {
        int m  = tid >> 3;               // 0..127
        int eo = tid & 7;                // 0..7 (lane bits 0..2)
        const float4* y = Y4 + (size_t)(b * M_ + m) * (D_ / 4);

        float u0 = 0.f, u1 = 0.f, u2 = 0.f, u3 = 0.f;
#pragma unroll
        for (int k = 0; k < 8; ++k) {
            int c = eo + 8 * k;          // float4 index, coalesced across eo
            float4 yv = y[c];
            float4 t0 = ts4[0][c], t1 = ts4[1][c], t2 = ts4[2][c], t3 = ts4[3][c];
            u0 = fmaf(t0.x, yv.x, u0); u0 = fmaf(t0.y, yv.y, u0);
            u0 = fmaf(t0.z, yv.z, u0); u0 = fmaf(t0.w, yv.w, u0);
            u1 = fmaf(t1.x, yv.x, u1); u1 = fmaf(t1.y, yv.y, u1);
            u1 = fmaf(t1.z, yv.z, u1); u1 = fmaf(t1.w, yv.w, u1);
            u2 = fmaf(t2.x, yv.x, u2); u2 = fmaf(t2.y, yv.y, u2);
            u2 = fmaf(t2.z, yv.z, u2); u2 = fmaf(t2.w, yv.w, u2);
            u3 = fmaf(t3.x, yv.x, u3); u3 = fmaf(t3.y, yv.y, u3);
            u3 = fmaf(t3.z, yv.z, u3); u3 = fmaf(t3.w, yv.w, u3);
        }
#pragma unroll
        for (int o = 4; o > 0; o >>= 1) {
            u0 += __shfl_xor_sync(0xFFFFFFFFu, u0, o);
            u1 += __shfl_xor_sync(0xFFFFFFFFu, u1, o);
            u2 += __shfl_xor_sync(0xFFFFFFFFu, u2, o);
            u3 += __shfl_xor_sync(0xFFFFFFFFu, u3, o);
        }
        if (eo == 0) {
            float bb = sbias;
            S[(size_t)(r0 + 0) * M_ + m] = u0 + bb;
            S[(size_t)(r0 + 1) * M_ + m] = u1 + bb;
            S[(size_t)(r0 + 2) * M_ + m] = u2 + bb;
            S[(size_t)(r0 + 3) * M_ + m] = u3 + bb;
        }
    }
}

// ---------------------------------------------------------------------------
extern "C" void kernel_launch(void* const* d_in, const int* in_sizes, int n_in,
                              void* d_out, int out_size)
{
    const float* X  = (const float*)d_in[0];   // [4,128,256]
    const float* Y  = (const float*)d_in[1];   // [4,128,256]
    const float* A  = (const float*)d_in[2];   // [256,256,1024]
    const float* W  = (const float*)d_in[3];   // [1,1024]
    const float* bb = (const float*)d_in[4];   // [1]
    float* S = (float*)d_out;                  // [4,128,128]

    float* Ap;  cudaGetSymbolAddress((void**)&Ap, g_Aprime);

    // K1: 65536 rows, 1 per warp, 8 warps/block -> 8192 blocks
    k1_fold_w<<<(D_ * D_) / 8, 256>>>((const float4*)A, (const float4*)W, Ap);

    // Fused tail as PDL secondary: pre-launches while k1 drains.
    cudaLaunchConfig_t cfg = {};
    cfg.gridDim  = dim3(R_ / 4);
    cfg.blockDim = dim3(1024);
    cfg.dynamicSmemBytes = 0;
    cfg.stream = 0;
    cudaLaunchAttribute attr[1];
    attr[0].id = cudaLaunchAttributeProgrammaticStreamSerialization;
    attr[0].val.programmaticStreamSerializationAllowed = 1;
    cfg.attrs = attr;
    cfg.numAttrs = 1;

    cudaError_t e = cudaLaunchKernelEx(&cfg, k23_fused,
        (const float4*)X, (const float*)Ap, (const float4*)Y, bb, S);
    if (e != cudaSuccess) {
        // Fallback: plain launch (device-side sync degenerates to a no-op
        // under normal stream ordering). Same work, deterministic.
        k23_fused<<<R_ / 4, 1024>>>((const float4*)X, Ap, (const float4*)Y, bb, S);
    }
}

// round 10
// speedup vs baseline: 1.4581x; 1.0457x over previous
#include <cuda_runtime.h>

// Shapes (fixed by the problem)
#define B_   4
#define N_   128
#define M_   128
#define D_   256
#define BD_  1024
#define R_   (B_ * N_)        // 512 flattened (b,n) rows

// Scratch (no cudaMalloc allowed)
__device__ float g_Aprime[D_ * D_];   // 256 KB: A'[d,e] = sum_k A[d,e,k]*W[k]

// ---------------------------------------------------------------------------
// Kernel 1: A'[row] = dot(A[row, :], W[:]); row = d*256 + e.
// ONE row per warp, linear 268 MB DRAM stream (measured 81% DRAM / 42.3us —
// at the practical roofline). __ldcs evict-first; W staged in smem.
// FROZEN — every modification attempt regressed or was neutral.
// ---------------------------------------------------------------------------
__global__ __launch_bounds__(256) void k1_fold_w(
    const float4* __restrict__ A4,   // [65536 rows][256 float4]
    const float4* __restrict__ W4,   // [256 float4]
    float* __restrict__ Ap)          // [65536]
{
    __shared__ float4 ws[BD_ / 4];   // 4 KB
    ws[threadIdx.x] = W4[threadIdx.x];
    __syncthreads();

    int warp = (blockIdx.x * blockDim.x + threadIdx.x) >> 5;   // 0..65535
    int lane = threadIdx.x & 31;
    const float4* row = A4 + (size_t)warp * (BD_ / 4);

    float s = 0.0f;
#pragma unroll
    for (int i = 0; i < 8; ++i) {
        float4 a = __ldcs(&row[lane + i * 32]);
        float4 w = ws[lane + i * 32];
        s += a.x * w.x + a.y * w.y;
        s += a.z * w.z + a.w * w.w;
    }
#pragma unroll
    for (int o = 16; o > 0; o >>= 1)
        s += __shfl_xor_sync(0xFFFFFFFFu, s, o);
    if (lane == 0) Ap[warp] = s;
}

// ---------------------------------------------------------------------------
// Fused tail (PDL secondary): per block 4 r-rows (same b), 1024 threads.
// Stage A issue-optimized: X tile kept as float4, read via warp-uniform
// LDS.128 broadcast -> per 4-d group: 4 coalesced LDG.32 + 4 LDS.128 +
// 16 FFMA (was 4 LDG + 16 scalar LDS + 16 FFMA).
// ---------------------------------------------------------------------------
__global__ __launch_bounds__(1024) void k23_fused(
    const float4* __restrict__ X4,   // [512][64] float4
    const float* __restrict__ Ap,    // [256*256]
    const float4* __restrict__ Y4,   // [512][64] float4
    const float* __restrict__ bias,  // [1]
    float* __restrict__ S)           // [512*128]
{
    int r0 = blockIdx.x * 4;
    int b  = r0 >> 7;
    int tid = threadIdx.x;

    __shared__ float4 xs4[4][D_ / 4];   // 4 KB  X tile (float4 layout)
    __shared__ float  ps[4][4][D_];     // 16 KB partials [dq][r][e]
    __shared__ float4 ts4[4][D_ / 4];   // 4 KB  final T rows
    __shared__ float  sbias;

    // ---- k1-independent prologue (overlaps primary under PDL) ----
    if (tid < 256) {                    // X tile: 4 rows x 64 float4
        int ri = tid >> 6, c = tid & 63;
        xs4[ri][c] = X4[(size_t)(r0 + ri) * (D_ / 4) + c];
    }
    if (tid == 0) sbias = bias[0];
    {   // prefetch this block's Y[b] slab (128 KB = 1024 lines) into L2
        const char* yb = (const char*)(Y4 + (size_t)b * M_ * (D_ / 4));
        asm volatile("prefetch.global.L2 [%0];" :: "l"(yb + (size_t)tid * 128));
    }

    // ---- wait for k1 (programmatic dependency; no-op if launched plainly) --
#if __CUDA_ARCH__ >= 900
    cudaGridDependencySynchronize();
#endif
    __syncthreads();

    // ---- Stage A: T[4][256] = X_tile @ A' ----
    {
        int e  = tid & 255;
        int dq = tid >> 8;               // 0..3 -> d in [dq*64, dq*64+64)
        const float* ap = Ap + (size_t)(dq * 64) * D_ + e;

        float a0 = 0.f, a1 = 0.f, a2 = 0.f, a3 = 0.f;
#pragma unroll 8
        for (int i = 0; i < 16; ++i) {   // 16 groups of 4 d
            int d4 = dq * 16 + i;
            float v0 = ap[(4 * i + 0) * D_];   // coalesced over e
            float v1 = ap[(4 * i + 1) * D_];
            float v2 = ap[(4 * i + 2) * D_];
            float v3 = ap[(4 * i + 3) * D_];
            float4 x0 = xs4[0][d4];            // warp-uniform LDS.128 broadcast
            float4 x1 = xs4[1][d4];
            float4 x2 = xs4[2][d4];
            float4 x3 = xs4[3][d4];
            a0 = fmaf(x0.x, v0, a0); a0 = fmaf(x0.y, v1, a0);
            a0 = fmaf(x0.z, v2, a0); a0 = fmaf(x0.w, v3, a0);
            a1 = fmaf(x1.x, v0, a1); a1 = fmaf(x1.y, v1, a1);
            a1 = fmaf(x1.z, v2, a1); a1 = fmaf(x1.w, v3, a1);
            a2 = fmaf(x2.x, v0, a2); a2 = fmaf(x2.y, v1, a2);
            a2 = fmaf(x2.z, v2, a2); a2 = fmaf(x2.w, v3, a2);
            a3 = fmaf(x3.x, v0, a3); a3 = fmaf(x3.y, v1, a3);
            a3 = fmaf(x3.z, v2, a3); a3 = fmaf(x3.w, v3, a3);
        }
        ps[dq][0][e] = a0;
        ps[dq][1][e] = a1;
        ps[dq][2][e] = a2;
        ps[dq][3][e] = a3;
    }
    __syncthreads();

    // reduce over dq: thread -> (r = tid>>8, e = tid&255)
    {
        int r = tid >> 8;
        int e = tid & 255;
        float s = ps[0][r][e] + ps[1][r][e] + ps[2][r][e] + ps[3][r][e];
        ((float*)ts4)[r * D_ + e] = s;
    }
    __syncthreads();

    // ---- Stage B: S[4][128] = T @ Y[b]^T + bias ----
    {
        int m  = tid >> 3;               // 0..127
        int eo = tid & 7;                // 0..7 (lane bits 0..2)
        const float4* y = Y4 + (size_t)(b * M_ + m) * (D_ / 4);

        float u0 = 0.f, u1 = 0.f, u2 = 0.f, u3 = 0.f;
#pragma unroll
        for (int k = 0; k < 8; ++k) {
            int c = eo + 8 * k;          // float4 index, coalesced across eo
            float4 yv = y[c];
            float4 t0 = ts4[0][c], t1 = ts4[1][c], t2 = ts4[2][c], t3 = ts4[3][c];
            u0 = fmaf(t0.x, yv.x, u0); u0 = fmaf(t0.y, yv.y, u0);
            u0 = fmaf(t0.z, yv.z, u0); u0 = fmaf(t0.w, yv.w, u0);
            u1 = fmaf(t1.x, yv.x, u1); u1 = fmaf(t1.y, yv.y, u1);
            u1 = fmaf(t1.z, yv.z, u1); u1 = fmaf(t1.w, yv.w, u1);
            u2 = fmaf(t2.x, yv.x, u2); u2 = fmaf(t2.y, yv.y, u2);
            u2 = fmaf(t2.z, yv.z, u2); u2 = fmaf(t2.w, yv.w, u2);
            u3 = fmaf(t3.x, yv.x, u3); u3 = fmaf(t3.y, yv.y, u3);
            u3 = fmaf(t3.z, yv.z, u3); u3 = fmaf(t3.w, yv.w, u3);
        }
#pragma unroll
        for (int o = 4; o > 0; o >>= 1) {
            u0 += __shfl_xor_sync(0xFFFFFFFFu, u0, o);
            u1 += __shfl_xor_sync(0xFFFFFFFFu, u1, o);
            u2 += __shfl_xor_sync(0xFFFFFFFFu, u2, o);
            u3 += __shfl_xor_sync(0xFFFFFFFFu, u3, o);
        }
        if (eo == 0) {
            float bb = sbias;
            S[(size_t)(r0 + 0) * M_ + m] = u0 + bb;
            S[(size_t)(r0 + 1) * M_ + m] = u1 + bb;
            S[(size_t)(r0 + 2) * M_ + m] = u2 + bb;
            S[(size_t)(r0 + 3) * M_ + m] = u3 + bb;
        }
    }
}

// ---------------------------------------------------------------------------
extern "C" void kernel_launch(void* const* d_in, const int* in_sizes, int n_in,
                              void* d_out, int out_size)
{
    const float* X  = (const float*)d_in[0];   // [4,128,256]
    const float* Y  = (const float*)d_in[1];   // [4,128,256]
    const float* A  = (const float*)d_in[2];   // [256,256,1024]
    const float* W  = (const float*)d_in[3];   // [1,1024]
    const float* bb = (const float*)d_in[4];   // [1]
    float* S = (float*)d_out;                  // [4,128,128]

    float* Ap;  cudaGetSymbolAddress((void**)&Ap, g_Aprime);

    // K1: 65536 rows, 1 per warp, 8 warps/block -> 8192 blocks
    k1_fold_w<<<(D_ * D_) / 8, 256>>>((const float4*)A, (const float4*)W, Ap);

    // Fused tail as PDL secondary: pre-launches while k1 drains.
    cudaLaunchConfig_t cfg = {};
    cfg.gridDim  = dim3(R_ / 4);
    cfg.blockDim = dim3(1024);
    cfg.dynamicSmemBytes = 0;
    cfg.stream = 0;
    cudaLaunchAttribute attr[1];
    attr[0].id = cudaLaunchAttributeProgrammaticStreamSerialization;
    attr[0].val.programmaticStreamSerializationAllowed = 1;
    cfg.attrs = attr;
    cfg.numAttrs = 1;

    cudaError_t e = cudaLaunchKernelEx(&cfg, k23_fused,
        (const float4*)X, (const float*)Ap, (const float4*)Y, bb, S);
    if (e != cudaSuccess) {
        // Fallback: plain launch (device-side sync degenerates to a no-op
        // under normal stream ordering). Same work, deterministic.
        k23_fused<<<R_ / 4, 1024>>>((const float4*)X, Ap, (const float4*)Y, bb, S);
    }
}